// round 8
// baseline (speedup 1.0000x reference)
#include <cuda_runtime.h>
#include <cuda_bf16.h>
#include <cstdint>
#include <cstring>

// DotProductAttention B=64,S=1024,D=64 fp32, 1-D valid_lens.
// Round 7: occupancy attack.
//  - pre-pass kernel converts K/V fp32 -> bf16 hi/lo ONCE per batch into a
//    __device__ scratch laid out exactly as the padded smem tiles
//  - main kernel loop fills smem via cp.async.cg (no conversion, no staging
//    registers) -> regs <= 128 -> 2 CTAs/SM -> 16 warps/SM
//  - 3-term bf16-split HMMA for both GEMMs (error budget: every correction
//    term is required; dropping any -> ~2e-3 rel err)

#define BATCH 64
#define SEQ   1024
#define DIM   64
#define TM    128
#define TN    64
#define NTH   256
#define LDS_  72

#define ABYTES    9216u      // one array: 64 rows * 72 shorts * 2B
#define BUFBYTES  36864u     // Khi,Klo,Vhi,Vlo
#define SMEMB     73728      // 2 buffers
#define NTILES_S  16

// scratch: per (batch,tile) one contiguous 36864B block, smem-identical layout
__device__ __align__(16) unsigned char g_scratch[(size_t)BATCH * NTILES_S * BUFBYTES];

static __device__ __forceinline__ void split2(float x0, float x1,
                                              uint32_t& hw, uint32_t& lw) {
    __nv_bfloat162 h = __floats2bfloat162_rn(x0, x1);
    memcpy(&hw, &h, 4);
    float h0 = __uint_as_float(hw << 16);
    float h1 = __uint_as_float(hw & 0xffff0000u);
    __nv_bfloat162 l = __floats2bfloat162_rn(x0 - h0, x1 - h1);
    memcpy(&lw, &l, 4);
}

static __device__ __forceinline__ void mma16816(float* c, const uint32_t* a,
                                                uint32_t b0, uint32_t b1) {
    asm volatile(
        "mma.sync.aligned.m16n8k16.row.col.f32.bf16.bf16.f32 "
        "{%0,%1,%2,%3}, {%4,%5,%6,%7}, {%8,%9}, {%0,%1,%2,%3};"
        : "+f"(c[0]), "+f"(c[1]), "+f"(c[2]), "+f"(c[3])
        : "r"(a[0]), "r"(a[1]), "r"(a[2]), "r"(a[3]), "r"(b0), "r"(b1));
}

static __device__ __forceinline__ void ldsm4(uint32_t* r, uint32_t addr) {
    asm volatile("ldmatrix.sync.aligned.m8n8.x4.shared.b16 {%0,%1,%2,%3}, [%4];"
                 : "=r"(r[0]), "=r"(r[1]), "=r"(r[2]), "=r"(r[3]) : "r"(addr));
}
static __device__ __forceinline__ void ldsm4t(uint32_t* r, uint32_t addr) {
    asm volatile("ldmatrix.sync.aligned.m8n8.x4.trans.shared.b16 {%0,%1,%2,%3}, [%4];"
                 : "=r"(r[0]), "=r"(r[1]), "=r"(r[2]), "=r"(r[3]) : "r"(addr));
}

static __device__ __forceinline__ uint32_t smem_u32(const void* p) {
    uint32_t a;
    asm("{ .reg .u64 t; cvta.to.shared.u64 t, %1; cvt.u32.u64 %0, t; }"
        : "=r"(a) : "l"(p));
    return a;
}

// ---------------- pre-pass: fp32 K/V -> bf16 hi/lo tile blocks ----------------
__global__ __launch_bounds__(NTH)
void prepass_kernel(const float* __restrict__ k, const float* __restrict__ v,
                    const int* __restrict__ vl) {
    const int b = blockIdx.x >> 4;
    const int t = blockIdx.x & 15;
    const int valid = vl[b];
    const int n = (valid == 0) ? SEQ : valid;
    if (t * TN >= n) return;     // masked-out tile: never read by main kernel

    const int tid = threadIdx.x;
    const float4* kg4 = (const float4*)(k + ((size_t)b * SEQ + t * TN) * DIM);
    const float4* vg4 = (const float4*)(v + ((size_t)b * SEQ + t * TN) * DIM);
    unsigned char* base = g_scratch + (size_t)(b * NTILES_S + t) * BUFBYTES;

    #pragma unroll
    for (int j = 0; j < 4; j++) {
        const int i = j * 256 + tid;
        const int off = (i >> 4) * 144 + (i & 15) * 8;
        float4 kk = __ldg(kg4 + i);
        float4 vv = __ldg(vg4 + i);
        uint32_t h01, l01, h23, l23;
        split2(kk.x, kk.y, h01, l01);
        split2(kk.z, kk.w, h23, l23);
        *(uint2*)(base + off)              = make_uint2(h01, h23);   // Khi
        *(uint2*)(base + ABYTES + off)     = make_uint2(l01, l23);   // Klo
        split2(vv.x, vv.y, h01, l01);
        split2(vv.z, vv.w, h23, l23);
        *(uint2*)(base + 2 * ABYTES + off) = make_uint2(h01, h23);   // Vhi
        *(uint2*)(base + 3 * ABYTES + off) = make_uint2(l01, l23);   // Vlo
    }
}

// ---------------- main kernel ----------------
__global__ __launch_bounds__(NTH, 2)
void attn_hmma6_kernel(const float* __restrict__ q, const int* __restrict__ vl,
                       float* __restrict__ out) {
    extern __shared__ char smc[];
    const int tid  = threadIdx.x;
    const int lane = tid & 31;
    const int wid  = tid >> 5;
    const int b    = blockIdx.x >> 3;
    const int qt   = blockIdx.x & 7;
    const int r0   = lane >> 2;
    const int m4   = lane & 3;

    const int  valid  = vl[b];
    const bool uni    = (valid == 0);
    const int  n      = uni ? SEQ : valid;
    const int  ntiles = (n + TN - 1) / TN;

    // ---- Q fragments (register-resident, pre-scaled by 1/8, hi/lo split)
    uint32_t qhi[4][4], qlo[4][4];
    {
        const float* qb = q + ((size_t)(b * SEQ + qt * TM + wid * 16)) * DIM;
        #pragma unroll
        for (int c = 0; c < 4; c++) {
            const int d0 = c * 16 + 2 * m4;
            float2 x00 = *(const float2*)(qb + r0 * DIM + d0);
            float2 x10 = *(const float2*)(qb + (r0 + 8) * DIM + d0);
            float2 x01 = *(const float2*)(qb + r0 * DIM + d0 + 8);
            float2 x11 = *(const float2*)(qb + (r0 + 8) * DIM + d0 + 8);
            split2(x00.x * 0.125f, x00.y * 0.125f, qhi[c][0], qlo[c][0]);
            split2(x10.x * 0.125f, x10.y * 0.125f, qhi[c][1], qlo[c][1]);
            split2(x01.x * 0.125f, x01.y * 0.125f, qhi[c][2], qlo[c][2]);
            split2(x11.x * 0.125f, x11.y * 0.125f, qhi[c][3], qlo[c][3]);
        }
    }

    float oac[8][4];
    #pragma unroll
    for (int g = 0; g < 8; g++)
        oac[g][0] = oac[g][1] = oac[g][2] = oac[g][3] = 0.0f;
    float lr0 = 0.0f, lr1 = 0.0f;

    const uint32_t sb = smem_u32(smc);
    const uint32_t koff =
        (uint32_t)(((((lane >> 4) & 1) * 8 + (lane & 7)) * LDS_ +
                    ((lane >> 3) & 1) * 8) * 2);
    const uint32_t voff =
        (uint32_t)(((((lane >> 3) & 1) * 8 + (lane & 7)) * LDS_ +
                    ((lane >> 4) & 1) * 8) * 2);

    const unsigned char* scr = g_scratch + (size_t)(b * NTILES_S) * BUFBYTES;

    // async bulk copy of one pre-converted tile block into smem buffer
#define CPA(T, BUF) do {                                                      \
    const unsigned long long src_ = (unsigned long long)                      \
        __cvta_generic_to_global(scr + (size_t)(T) * BUFBYTES);               \
    const uint32_t dst_ = sb + (uint32_t)(BUF) * BUFBYTES;                    \
    _Pragma("unroll")                                                         \
    for (int i_ = 0; i_ < 9; i_++) {                                          \
        const uint32_t o_ = (uint32_t)(i_ * 256 + tid) * 16u;                 \
        asm volatile("cp.async.cg.shared.global [%0], [%1], 16;"              \
                     :: "r"(dst_ + o_), "l"(src_ + o_) : "memory");           \
    } } while (0)
#define CPA_COMMIT() asm volatile("cp.async.commit_group;" ::: "memory")
#define CPA_WAIT1()  asm volatile("cp.async.wait_group 1;" ::: "memory")

    CPA(0, 0);
    CPA_COMMIT();
    if (ntiles > 1) CPA(1, 1);
    CPA_COMMIT();            // committed even if empty: keeps group count aligned
    CPA_WAIT1();             // tile 0 resident
    __syncthreads();

    for (int t = 0; t < ntiles; t++) {
        const uint32_t kh = sb + (uint32_t)(t & 1) * BUFBYTES + koff;
        const uint32_t vh = sb + (uint32_t)(t & 1) * BUFBYTES + 2 * ABYTES + voff;

        // ---- QK^T (3-term bf16 split)
        float sa[8][4];
        #pragma unroll
        for (int g = 0; g < 8; g++)
            sa[g][0] = sa[g][1] = sa[g][2] = sa[g][3] = 0.0f;
        #pragma unroll
        for (int c = 0; c < 4; c++) {
            #pragma unroll
            for (int gp = 0; gp < 4; gp++) {
                uint32_t fh[4], fl[4];
                const uint32_t ka = kh + gp * 2304 + c * 32;
                ldsm4(fh, ka);
                ldsm4(fl, ka + ABYTES);
                mma16816(sa[2 * gp],     qhi[c], fh[0], fh[1]);
                mma16816(sa[2 * gp + 1], qhi[c], fh[2], fh[3]);
                mma16816(sa[2 * gp],     qlo[c], fh[0], fh[1]);
                mma16816(sa[2 * gp + 1], qlo[c], fh[2], fh[3]);
                mma16816(sa[2 * gp],     qhi[c], fl[0], fl[1]);
                mma16816(sa[2 * gp + 1], qhi[c], fl[2], fl[3]);
            }
        }

        // ---- softmax (no max); masking at tile granularity
        uint32_t PH[8][2], PL[8][2];
        const int jt = t * TN;
        if (!uni) {
            if (jt + TN <= n) {
                #pragma unroll
                for (int g = 0; g < 8; g++) {
                    const float p0 = __expf(sa[g][0]);
                    const float p1 = __expf(sa[g][1]);
                    const float p2 = __expf(sa[g][2]);
                    const float p3 = __expf(sa[g][3]);
                    lr0 += p0 + p1;
                    lr1 += p2 + p3;
                    split2(p0, p1, PH[g][0], PL[g][0]);
                    split2(p2, p3, PH[g][1], PL[g][1]);
                }
            } else {
                #pragma unroll
                for (int g = 0; g < 8; g++) {
                    const int j0 = jt + g * 8 + 2 * m4;
                    const float p0 = (j0     < n) ? __expf(sa[g][0]) : 0.0f;
                    const float p1 = (j0 + 1 < n) ? __expf(sa[g][1]) : 0.0f;
                    const float p2 = (j0     < n) ? __expf(sa[g][2]) : 0.0f;
                    const float p3 = (j0 + 1 < n) ? __expf(sa[g][3]) : 0.0f;
                    lr0 += p0 + p1;
                    lr1 += p2 + p3;
                    split2(p0, p1, PH[g][0], PL[g][0]);
                    split2(p2, p3, PH[g][1], PL[g][1]);
                }
            }
        } else {
            #pragma unroll
            for (int g = 0; g < 8; g++) {
                lr0 += 2.0f;
                lr1 += 2.0f;
                PH[g][0] = PH[g][1] = 0x3F803F80u;
                PL[g][0] = PL[g][1] = 0u;
            }
        }

        // ---- P @ V (3-term bf16 split, V fragments via ldmatrix.trans)
        #pragma unroll
        for (int kc = 0; kc < 4; kc++) {
            const uint32_t ah[4] = {PH[2 * kc][0], PH[2 * kc][1],
                                    PH[2 * kc + 1][0], PH[2 * kc + 1][1]};
            const uint32_t al[4] = {PL[2 * kc][0], PL[2 * kc][1],
                                    PL[2 * kc + 1][0], PL[2 * kc + 1][1]};
            #pragma unroll
            for (int gp = 0; gp < 4; gp++) {
                uint32_t fh[4], fl[4];
                const uint32_t va = vh + kc * 2304 + gp * 32;
                ldsm4t(fh, va);
                ldsm4t(fl, va + ABYTES);
                mma16816(oac[2 * gp],     ah, fh[0], fh[1]);
                mma16816(oac[2 * gp + 1], ah, fh[2], fh[3]);
                mma16816(oac[2 * gp],     al, fh[0], fh[1]);
                mma16816(oac[2 * gp + 1], al, fh[2], fh[3]);
                mma16816(oac[2 * gp],     ah, fl[0], fl[1]);
                mma16816(oac[2 * gp + 1], ah, fl[2], fl[3]);
            }
        }

        // ---- rotate pipeline: refill the buffer just consumed with tile t+2
        __syncthreads();                       // all warps done reading buf t&1
        if (t + 2 < ntiles) CPA(t + 2, t & 1);
        CPA_COMMIT();
        CPA_WAIT1();                           // tile t+1 resident
        __syncthreads();
    }

    // ---- epilogue
    lr0 += __shfl_xor_sync(0xffffffffu, lr0, 1);
    lr0 += __shfl_xor_sync(0xffffffffu, lr0, 2);
    lr1 += __shfl_xor_sync(0xffffffffu, lr1, 1);
    lr1 += __shfl_xor_sync(0xffffffffu, lr1, 2);
    const float inv0 = 1.0f / lr0;
    const float inv1 = 1.0f / lr1;

    float* ob = out + ((size_t)(b * SEQ + qt * TM + wid * 16)) * DIM;
    #pragma unroll
    for (int g = 0; g < 8; g++) {
        const int d0 = g * 8 + 2 * m4;
        *(float2*)(ob + r0 * DIM + d0) =
            make_float2(oac[g][0] * inv0, oac[g][1] * inv0);
        *(float2*)(ob + (r0 + 8) * DIM + d0) =
            make_float2(oac[g][2] * inv1, oac[g][3] * inv1);
    }
}

extern "C" void kernel_launch(void* const* d_in, const int* in_sizes, int n_in,
                              void* d_out, int out_size) {
    const float* q  = (const float*)d_in[0];
    const float* k  = (const float*)d_in[1];
    const float* v  = (const float*)d_in[2];
    const int*   vl = (const int*)d_in[3];
    float*       o  = (float*)d_out;

    prepass_kernel<<<BATCH * NTILES_S, NTH>>>(k, v, vl);

    cudaFuncSetAttribute(attn_hmma6_kernel,
                         cudaFuncAttributeMaxDynamicSharedMemorySize, SMEMB);
    attn_hmma6_kernel<<<BATCH * (SEQ / TM), NTH, SMEMB>>>(q, vl, o);
}